// round 17
// baseline (speedup 1.0000x reference)
#include <cuda_runtime.h>

// SoftBoundDDM_RT: 4096 trials x 2000-step leaky-DDM recurrence + soft bounds.
// TWO warps per trial, balanced split at 1280, UNIFIED role loop (runtime trip
// counts) to minimize register pressure and maximize resident warps:
//   warp A: reduce 0 rounds,  outputs [0,1280)    (10 rounds, all full)
//   warp B: reduce 10 rounds, outputs [1280,2000) (5 full + 80-elem tail)
// Reduce is an order-independent weighted sum (no scan, one butterfly).
// No smem, no __syncthreads. Linear recurrence as weighted prefix SUM:
//   e[T] = D^T * ( e0 + sum_{i<T} u[i] * D^-(i+1) ),  D = 0.99999.

constexpr int   N_T    = 2000;
constexpr int   SPLIT  = 1280;
constexpr int   TPB    = 128;         // 4 warps = 2 trials per block
constexpr float DT     = 0.001f;
constexpr float LEAK   = 0.01f;
constexpr float TC     = 0.01f;       // TIME_CONSTANT
constexpr float DECAY  = 1.0f - LEAK * DT;             // 0.99999
constexpr float DINV   = 1.0f / DECAY;
constexpr float LN_D   = -1.0000050000333e-5f;         // ln(0.99999)
constexpr float SQVDT  = 0.03162277660168379332f;      // sqrt(VARIANCE*DT)
constexpr float D128   = 0.99872081245862f;            // DECAY^128
constexpr float DI128  = 1.00128082595776f;            // DECAY^-128

// D^k for k=0..3 (immediates)
constexpr float DP1 = 0.99999f;
constexpr float DP2 = 0.9999800001f;
constexpr float DP3 = 0.9999700003f;

__device__ __forceinline__ float tanh_fast(float x) {
    float y;
    asm("tanh.approx.f32 %0, %1;" : "=f"(y) : "f"(x));
    return y;
}

__global__ __launch_bounds__(TPB, 10)
void ddm_kernel(const float* __restrict__ stim,
                const float* __restrict__ noise,
                const float* __restrict__ pa,
                const float* __restrict__ pz,
                const float* __restrict__ pg,
                const float* __restrict__ po,
                const float* __restrict__ pb,
                float* __restrict__ out,
                long long total_elems,      // n_trials * N_T
                int n_trials)
{
    const int lane  = threadIdx.x & 31;
    const int warp  = threadIdx.x >> 5;
    const int half  = warp & 1;                    // 0: warp A, 1: warp B
    const int trial = blockIdx.x * 2 + (warp >> 1);
    if (trial >= n_trials) return;

    const float a    = __ldg(pa);
    const float z    = __ldg(pz);
    const float g    = __ldg(pg);
    const float off  = __ldg(po);
    const float beta = __ldg(pb);

    const float e0     = z * a;
    const float cstim  = g * DT;
    const float cconst = off * DT + LEAK * e0 * DT;
    const float hb     = 0.5f * beta;         // sigmoid(x)=0.5+0.5*tanh(x/2)
    const float hba    = hb * a;

    const size_t tb = (size_t)trial * N_T;
    const float* sp = stim  + tb;
    const float* np = noise + tb;
    float* dvout = out + tb;
    const size_t OFS = (size_t)total_elems;

    const int lane4 = lane * 4;

    // per-role parameters (uniform within a warp)
    const int  redRounds = half ? 10 : 0;          // reduce over [0,1280)
    const int  outBase   = half ? SPLIT : 0;
    const int  outRounds = half ? 6 : 10;          // B: 5 full + 80-elem tail
    const bool tailOK    = (!half) || (lane < 20); // tail predicate (B only)

    // ================= reduce phase (order-independent weighted sum) ========
    float acc = 0.0f;
    {
        float Fr = __expf(-LN_D * (float)lane4);
        for (int r = 0; r < redRounds; r++) {
            const int pos = r * 128 + lane4;
            const float4 s4 = *reinterpret_cast<const float4*>(sp + pos);
            const float4 n4 = *reinterpret_cast<const float4*>(np + pos);
            const float u0 = fmaf(cstim, s4.x, fmaf(SQVDT, n4.x, cconst));
            const float u1 = fmaf(cstim, s4.y, fmaf(SQVDT, n4.y, cconst));
            const float u2 = fmaf(cstim, s4.z, fmaf(SQVDT, n4.z, cconst));
            const float u3 = fmaf(cstim, s4.w, fmaf(SQVDT, n4.w, cconst));
            float loc = u0 * DINV;
            loc = fmaf(u1, DINV * DINV, loc);
            loc = fmaf(u2, DINV * DINV * DINV, loc);
            loc = fmaf(u3, DINV * DINV * DINV * DINV, loc);
            acc = fmaf(Fr, loc, acc);
            Fr *= DI128;
        }
        if (half) {
            #pragma unroll
            for (int d = 16; d >= 1; d >>= 1)
                acc += __shfl_xor_sync(0xffffffffu, acc, d);
        }
    }
    float eR = e0 + acc;       // e0 + weighted sum of everything before outBase

    // ======================= output phase ===================================
    const int pos0 = outBase + lane4;
    float Gd = __expf(LN_D * (float)pos0);
    float F  = __expf(-LN_D * (float)pos0);

    // depth-1 prefetch (round 0 of a role is always fully live)
    float4 sA = *reinterpret_cast<const float4*>(sp + pos0);
    float4 nA = *reinterpret_cast<const float4*>(np + pos0);

    for (int r = 0; r < outRounds; r++) {
        const int  pos  = outBase + r * 128 + lane4;
        const bool live = (r < outRounds - 1) || tailOK;

        // prefetch next round before consuming this one
        float4 sB = make_float4(0.f, 0.f, 0.f, 0.f);
        float4 nB = make_float4(0.f, 0.f, 0.f, 0.f);
        if (r + 1 < outRounds) {
            const bool liveN = (r + 1 < outRounds - 1) || tailOK;
            if (liveN) {
                sB = __ldcs(reinterpret_cast<const float4*>(sp + pos + 128));
                nB = __ldcs(reinterpret_cast<const float4*>(np + pos + 128));
            }
        }

        // u and local weighted prefix q_k = sum_{j<=k} u_j * DINV^(j+1)
        const float u0 = fmaf(cstim, sA.x, fmaf(SQVDT, nA.x, cconst));
        const float u1 = fmaf(cstim, sA.y, fmaf(SQVDT, nA.y, cconst));
        const float u2 = fmaf(cstim, sA.z, fmaf(SQVDT, nA.z, cconst));
        const float u3 = fmaf(cstim, sA.w, fmaf(SQVDT, nA.w, cconst));
        const float q0 = u0 * DINV;
        const float q1 = fmaf(u1, DINV * DINV, q0);
        const float q2 = fmaf(u2, DINV * DINV * DINV, q1);
        const float q3 = fmaf(u3, DINV * DINV * DINV * DINV, q2);

        const float c = live ? F * q3 : 0.0f;

        // inclusive warp add-scan (independent of carry eR)
        float si = c;
        #pragma unroll
        for (int d = 1; d < 32; d <<= 1) {
            const float o = __shfl_up_sync(0xffffffffu, si, d);
            if (lane >= d) si += o;
        }
        const float ex  = si - c;
        const float tot = __shfl_sync(0xffffffffu, si, 31);

        const float basev = eR + ex;

        const float i0 = basev;
        const float i1 = fmaf(F, q0, basev);
        const float i2 = fmaf(F, q1, basev);
        const float i3 = fmaf(F, q2, basev);

        const float ev0 = Gd * i0;
        const float ev1 = Gd * (DP1 * i1);
        const float ev2 = Gd * (DP2 * i2);
        const float ev3 = Gd * (DP3 * i3);

        const float fp  = (float)pos;
        const float dv0 = fmaf(fp * TC,          ev0 - e0, e0);
        const float dv1 = fmaf((fp + 1.f) * TC,  ev1 - e0, e0);
        const float dv2 = fmaf((fp + 2.f) * TC,  ev2 - e0, e0);
        const float dv3 = fmaf((fp + 3.f) * TC,  ev3 - e0, e0);

        if (live) {
            float* dp = dvout + pos;
            __stcs(reinterpret_cast<float4*>(dp),
                   make_float4(dv0, dv1, dv2, dv3));
            // h1 = 0.5 + 0.5*tanh(hb*dv - hba)
            const float t10 = tanh_fast(fmaf(hb, dv0, -hba));
            const float t11 = tanh_fast(fmaf(hb, dv1, -hba));
            const float t12 = tanh_fast(fmaf(hb, dv2, -hba));
            const float t13 = tanh_fast(fmaf(hb, dv3, -hba));
            __stcs(reinterpret_cast<float4*>(dp + OFS),
                   make_float4(fmaf(0.5f, t10, 0.5f), fmaf(0.5f, t11, 0.5f),
                               fmaf(0.5f, t12, 0.5f), fmaf(0.5f, t13, 0.5f)));
            // h0 = 0.5 - 0.5*tanh(hb*dv)
            const float t00 = tanh_fast(hb * dv0);
            const float t01 = tanh_fast(hb * dv1);
            const float t02 = tanh_fast(hb * dv2);
            const float t03 = tanh_fast(hb * dv3);
            __stcs(reinterpret_cast<float4*>(dp + 2 * OFS),
                   make_float4(fmaf(-0.5f, t00, 0.5f), fmaf(-0.5f, t01, 0.5f),
                               fmaf(-0.5f, t02, 0.5f), fmaf(-0.5f, t03, 0.5f)));
        }

        eR += tot;                    // the ONLY cross-round dependency
        F  *= DI128;
        Gd *= D128;
        sA = sB;
        nA = nB;
    }
}

extern "C" void kernel_launch(void* const* d_in, const int* in_sizes, int n_in,
                              void* d_out, int out_size)
{
    const float* stim  = (const float*)d_in[0];
    const float* noise = (const float*)d_in[1];
    const float* pa    = (const float*)d_in[2];
    const float* pz    = (const float*)d_in[3];
    const float* pg    = (const float*)d_in[4];
    const float* po    = (const float*)d_in[5];
    const float* pb    = (const float*)d_in[6];
    float* out = (float*)d_out;

    const long long total = in_sizes[0];          // n_trials * N_T
    const int n_trials = (int)(total / N_T);
    const int n_blocks = (n_trials + 1) / 2;      // 2 trials per block

    ddm_kernel<<<n_blocks, TPB>>>(stim, noise, pa, pz, pg, po, pb, out, total, n_trials);
}